// round 2
// baseline (speedup 1.0000x reference)
#include <cuda_runtime.h>
#include <cstdint>

#define BB 32
#define SS 512
#define DD 768
#define SQ 511
#define NROWS (BB*SQ)

#define NEG_INF __int_as_float(0xff800000)

// Scratch (allocation-free rule: __device__ globals)
__device__ float g_invn[NROWS];
__device__ int   g_idx[NROWS];
__device__ float g_txt_sum;
__device__ float g_img_sum;
__device__ int   g_valid;

__global__ void k_zero() {
    g_txt_sum = 0.f; g_img_sum = 0.f; g_valid = 0;
}

// One warp per tgt row: invn[b,j] = rsqrt(sum_d target[b, j+1, d]^2)
__global__ void k_invnorm(const float* __restrict__ target) {
    int row = blockIdx.x * (blockDim.x >> 5) + (threadIdx.x >> 5);
    if (row >= NROWS) return;
    int lane = threadIdx.x & 31;
    int b = row / SQ, j = row % SQ;
    const float4* p = reinterpret_cast<const float4*>(
        target + (size_t)b * SS * DD + (size_t)(j + 1) * DD);
    float s = 0.f;
#pragma unroll
    for (int it = 0; it < DD / 128; it++) {
        float4 v = p[lane + it * 32];
        s += v.x * v.x + v.y * v.y + v.z * v.z + v.w * v.w;
    }
#pragma unroll
    for (int o = 16; o > 0; o >>= 1) s += __shfl_xor_sync(0xffffffffu, s, o);
    if (lane == 0) g_invn[row] = rsqrtf(s);
}

// Fused tiled SGEMM + online argmax.
// Block: 64 i-rows x (all j in 64-tiles), 256 threads as 16x16, 4x4 microtile.
#define TI 64
#define TJ 64
#define TK 32

__global__ __launch_bounds__(256) void k_argmax(const float* __restrict__ text,
                                                const float* __restrict__ target) {
    __shared__ float As[TI][TK + 1];
    __shared__ float Bs[TJ][TK + 1];
    __shared__ float Inv[TJ];

    int b  = blockIdx.y;
    int i0 = blockIdx.x * TI;
    const float* txt = text   + (size_t)b * SS * DD + DD;  // row i -> text[b][i+1]
    const float* tgt = target + (size_t)b * SS * DD + DD;

    int tid = threadIdx.x;
    int tx = tid & 15, ty = tid >> 4;

    float best[4];
    int   bidx[4];
#pragma unroll
    for (int ii = 0; ii < 4; ii++) { best[ii] = NEG_INF; bidx[ii] = 0; }

    for (int j0 = 0; j0 < SQ; j0 += TJ) {
        __syncthreads();  // protect Inv from previous epilogue readers
        if (tid < TJ) {
            int j = j0 + tid;
            Inv[tid] = (j < SQ) ? g_invn[b * SQ + j] : 0.f;
        }

        float acc[4][4];
#pragma unroll
        for (int a = 0; a < 4; a++)
#pragma unroll
            for (int c = 0; c < 4; c++) acc[a][c] = 0.f;

        for (int k0 = 0; k0 < DD; k0 += TK) {
            __syncthreads();
            // Load A tile: 64 x 32 floats = 512 float4s, 2 per thread
#pragma unroll
            for (int l = 0; l < 2; l++) {
                int li  = tid + l * 256;
                int row = li >> 3;
                int col = (li & 7) * 4;
                int gi  = i0 + row;
                float4 v = make_float4(0.f, 0.f, 0.f, 0.f);
                if (gi < SQ)
                    v = *reinterpret_cast<const float4*>(txt + (size_t)gi * DD + k0 + col);
                As[row][col] = v.x; As[row][col + 1] = v.y;
                As[row][col + 2] = v.z; As[row][col + 3] = v.w;
            }
#pragma unroll
            for (int l = 0; l < 2; l++) {
                int li  = tid + l * 256;
                int row = li >> 3;
                int col = (li & 7) * 4;
                int gj  = j0 + row;
                float4 v = make_float4(0.f, 0.f, 0.f, 0.f);
                if (gj < SQ)
                    v = *reinterpret_cast<const float4*>(tgt + (size_t)gj * DD + k0 + col);
                Bs[row][col] = v.x; Bs[row][col + 1] = v.y;
                Bs[row][col + 2] = v.z; Bs[row][col + 3] = v.w;
            }
            __syncthreads();

#pragma unroll
            for (int kk = 0; kk < TK; kk++) {
                float a[4], bv[4];
#pragma unroll
                for (int ii = 0; ii < 4; ii++) a[ii] = As[ty * 4 + ii][kk];
#pragma unroll
                for (int jj = 0; jj < 4; jj++) bv[jj] = Bs[tx * 4 + jj][kk];
#pragma unroll
                for (int ii = 0; ii < 4; ii++)
#pragma unroll
                    for (int jj = 0; jj < 4; jj++)
                        acc[ii][jj] = fmaf(a[ii], bv[jj], acc[ii][jj]);
            }
        }

        // Epilogue: scale by invn[j], argmax over this j-tile, fold into running best.
#pragma unroll
        for (int ii = 0; ii < 4; ii++) {
            float v = NEG_INF;
            int   id = 0;
#pragma unroll
            for (int jj = 0; jj < 4; jj++) {
                int j = j0 + tx * 4 + jj;
                float s = (j < SQ) ? acc[ii][jj] * Inv[tx * 4 + jj] : NEG_INF;
                if (s > v) { v = s; id = j; }
            }
            // reduce across the 16 tx lanes (low 4 lane bits)
#pragma unroll
            for (int o = 8; o > 0; o >>= 1) {
                float ov  = __shfl_xor_sync(0xffffffffu, v, o);
                int   oid = __shfl_xor_sync(0xffffffffu, id, o);
                if (ov > v || (ov == v && oid < id)) { v = ov; id = oid; }
            }
            if (tx == 0) {
                if (v > best[ii] || (v == best[ii] && id < bidx[ii])) {
                    best[ii] = v; bidx[ii] = id;
                }
            }
        }
    }

    if (tx == 0) {
#pragma unroll
        for (int ii = 0; ii < 4; ii++) {
            int gi = i0 + ty * 4 + ii;
            if (gi < SQ) g_idx[b * SQ + gi] = bidx[ii];
        }
    }
}

// Image MSE sum: grid-stride float4, block reduce, one atomic per block.
__global__ void k_imgloss(const float* __restrict__ image,
                          const float* __restrict__ target) {
    const int N4 = BB * SS * DD / 4;
    float s = 0.f;
    for (int i = blockIdx.x * blockDim.x + threadIdx.x; i < N4;
         i += gridDim.x * blockDim.x) {
        float4 a = reinterpret_cast<const float4*>(image)[i];
        float4 t = reinterpret_cast<const float4*>(target)[i];
        float dx = a.x - t.x, dy = a.y - t.y, dz = a.z - t.z, dw = a.w - t.w;
        s += dx * dx + dy * dy + dz * dz + dw * dw;
    }
#pragma unroll
    for (int o = 16; o > 0; o >>= 1) s += __shfl_xor_sync(0xffffffffu, s, o);
    __shared__ float warp_s[8];
    int wid = threadIdx.x >> 5, lane = threadIdx.x & 31;
    if (lane == 0) warp_s[wid] = s;
    __syncthreads();
    if (wid == 0) {
        s = (lane < (blockDim.x >> 5)) ? warp_s[lane] : 0.f;
#pragma unroll
        for (int o = 4; o > 0; o >>= 1) s += __shfl_xor_sync(0xffffffffu, s, o);
        if (lane == 0) atomicAdd(&g_img_sum, s);
    }
}

// Text loss: one warp per row; gather aligned = tgt[idx], masked sq-diff sum.
__global__ void k_txtloss(const float* __restrict__ text,
                          const float* __restrict__ target,
                          const int* __restrict__ pm) {
    int row = blockIdx.x * (blockDim.x >> 5) + (threadIdx.x >> 5);
    if (row >= NROWS) return;
    int lane = threadIdx.x & 31;
    int b = row / SQ, i = row % SQ;
    if (pm[b * SS + i + 1] != 0) return;
    int id = g_idx[row];
    const float4* pt = reinterpret_cast<const float4*>(
        text + (size_t)b * SS * DD + (size_t)(i + 1) * DD);
    const float4* pa = reinterpret_cast<const float4*>(
        target + (size_t)b * SS * DD + (size_t)(id + 1) * DD);
    float s = 0.f;
#pragma unroll
    for (int it = 0; it < DD / 128; it++) {
        float4 a = pt[lane + it * 32];
        float4 c = pa[lane + it * 32];
        float dx = a.x - c.x, dy = a.y - c.y, dz = a.z - c.z, dw = a.w - c.w;
        s += dx * dx + dy * dy + dz * dz + dw * dw;
    }
#pragma unroll
    for (int o = 16; o > 0; o >>= 1) s += __shfl_xor_sync(0xffffffffu, s, o);
    if (lane == 0) {
        atomicAdd(&g_txt_sum, s);
        atomicAdd(&g_valid, 1);
    }
}

__global__ void k_finalize(float* __restrict__ out) {
    float kt = g_txt_sum / ((float)g_valid * (float)DD);
    float ki = g_img_sum / (float)(BB * SS * DD);
    out[0] = 0.5f * (kt + ki);
    out[1] = kt;
    out[2] = ki;
}

__global__ void k_idxcopy(float* __restrict__ out) {
    int n = blockIdx.x * blockDim.x + threadIdx.x;
    if (n < NROWS) out[3 + n] = (float)g_idx[n];
}

extern "C" void kernel_launch(void* const* d_in, const int* in_sizes, int n_in,
                              void* d_out, int out_size) {
    const float* image  = (const float*)d_in[0];
    const float* text   = (const float*)d_in[1];
    const float* target = (const float*)d_in[2];
    const int*   pm     = (const int*)d_in[3];
    float* out = (float*)d_out;

    k_zero<<<1, 1>>>();
    k_invnorm<<<(NROWS + 3) / 4, 128>>>(target);
    {
        dim3 grid((SQ + TI - 1) / TI, BB);
        k_argmax<<<grid, 256>>>(text, target);
    }
    k_imgloss<<<1184, 256>>>(image, target);
    k_txtloss<<<(NROWS + 3) / 4, 128>>>(text, target, pm);
    k_finalize<<<1, 1>>>(out);
    k_idxcopy<<<(NROWS + 255) / 256, 256>>>(out);
}

// round 4
// speedup vs baseline: 1.1472x; 1.1472x over previous
#include <cuda_runtime.h>
#include <cuda_bf16.h>
#include <cstdint>

#define BB 32
#define SS 512
#define DD 768
#define SQ 511
#define NROWS (BB*SQ)
#define NEG_INF __int_as_float(0xff800000)

#define CHUNKS 72          // K = 6*768 = 4608, chunks of 64
#define BLK_U4 1024        // 128 rows * 64 bf16 * 2B / 16B

// prepped tiles: [b][tile(0..3)][chunk][128 rows x 64 bf16, swizzled]
__device__ uint4 g_Apre[(size_t)BB * 4 * CHUNKS * BLK_U4];
__device__ uint4 g_Bpre[(size_t)BB * 4 * CHUNKS * BLK_U4];
__device__ float g_invn[NROWS];
__device__ unsigned long long g_pack[NROWS];
__device__ int   g_idx[NROWS];
__device__ float g_txt_sum;
__device__ float g_img_sum;
__device__ int   g_valid;

__device__ __forceinline__ uint32_t smem_u32(const void* p) {
    uint32_t a;
    asm("{ .reg .u64 t; cvta.to.shared.u64 t, %1; cvt.u32.u64 %0, t; }"
        : "=r"(a) : "l"(p));
    return a;
}

// ============================ init ============================

__global__ void k_init() {
    int n = blockIdx.x * blockDim.x + threadIdx.x;
    if (n < NROWS) g_pack[n] = 0ull;   // any real packed value > 0
    if (n == 0) { g_txt_sum = 0.f; g_img_sum = 0.f; g_valid = 0; }
}

// ============================ invnorm ============================

__global__ void k_invnorm(const float* __restrict__ target) {
    int row = blockIdx.x * (blockDim.x >> 5) + (threadIdx.x >> 5);
    if (row >= NROWS) return;
    int lane = threadIdx.x & 31;
    int b = row / SQ, j = row % SQ;
    const float4* p = reinterpret_cast<const float4*>(
        target + (size_t)b * SS * DD + (size_t)(j + 1) * DD);
    float s = 0.f;
#pragma unroll
    for (int it = 0; it < DD / 128; it++) {
        float4 v = p[lane + it * 32];
        s += v.x * v.x + v.y * v.y + v.z * v.z + v.w * v.w;
    }
#pragma unroll
    for (int o = 16; o > 0; o >>= 1) s += __shfl_xor_sync(0xffffffffu, s, o);
    if (lane == 0) g_invn[row] = rsqrtf(s);
}

// ============================ prep ============================
// split fp32 -> bf16 hi/mid/lo; K-concat 6 groups.
// A groups: hi,hi,hi,mid,mid,lo    B groups: hi,mid,lo,hi,mid,hi
// (covers hh + hm + hl + mh + mm + lh; residual ~2^-24)

__device__ __forceinline__ uint4 pack8(const unsigned short* u) {
    uint4 v;
    v.x = (uint32_t)u[0] | ((uint32_t)u[1] << 16);
    v.y = (uint32_t)u[2] | ((uint32_t)u[3] << 16);
    v.z = (uint32_t)u[4] | ((uint32_t)u[5] << 16);
    v.w = (uint32_t)u[6] | ((uint32_t)u[7] << 16);
    return v;
}

__device__ __forceinline__ void split8(const float* x, uint4& vh, uint4& vm, uint4& vl) {
    unsigned short h[8], m[8], l[8];
#pragma unroll
    for (int q = 0; q < 8; q++) {
        __nv_bfloat16 bh = __float2bfloat16(x[q]);
        float r1 = x[q] - __bfloat162float(bh);
        __nv_bfloat16 bm = __float2bfloat16(r1);
        float r2 = r1 - __bfloat162float(bm);
        __nv_bfloat16 bl = __float2bfloat16(r2);
        h[q] = __bfloat16_as_ushort(bh);
        m[q] = __bfloat16_as_ushort(bm);
        l[q] = __bfloat16_as_ushort(bl);
    }
    vh = pack8(h); vm = pack8(m); vl = pack8(l);
}

// granule layout inside a 128x64 tile: uint4_idx = row*8 + (kg ^ (row&7))
__device__ __forceinline__ void prep_store(uint4* base, int r, int c, int kg, uint4 v) {
    int tile = r >> 7, row = r & 127;
    base[((size_t)tile * CHUNKS + c) * BLK_U4 + row * 8 + (kg ^ (row & 7))] = v;
}

__global__ void k_prep_A(const float* __restrict__ text) {
    int item = blockIdx.x * blockDim.x + threadIdx.x;   // BB*512*96
    if (item >= BB * 512 * 96) return;
    int ks = item % 96;
    int r  = (item / 96) & 511;
    int b  = item / (96 * 512);
    float x[8];
    if (r < SQ) {
        const float* src = text + ((size_t)b * SS + r + 1) * DD + ks * 8;
#pragma unroll
        for (int q = 0; q < 8; q++) x[q] = src[q];
    } else {
#pragma unroll
        for (int q = 0; q < 8; q++) x[q] = 0.f;
    }
    uint4 vh, vm, vl;
    split8(x, vh, vm, vl);
    uint4* base = g_Apre + (size_t)b * 4 * CHUNKS * BLK_U4;
#pragma unroll
    for (int g = 0; g < 6; g++) {
        uint4 v = (g < 3) ? vh : ((g < 5) ? vm : vl);
        int k6 = g * DD + ks * 8;
        prep_store(base, r, k6 >> 6, (k6 & 63) >> 3, v);
    }
}

__global__ void k_prep_B(const float* __restrict__ target) {
    int item = blockIdx.x * blockDim.x + threadIdx.x;
    if (item >= BB * 512 * 96) return;
    int ks = item % 96;
    int r  = (item / 96) & 511;
    int b  = item / (96 * 512);
    float x[8];
    if (r < SQ) {
        const float* src = target + ((size_t)b * SS + r + 1) * DD + ks * 8;
#pragma unroll
        for (int q = 0; q < 8; q++) x[q] = src[q];
    } else {
#pragma unroll
        for (int q = 0; q < 8; q++) x[q] = 0.f;
    }
    uint4 vh, vm, vl;
    split8(x, vh, vm, vl);
    uint4* base = g_Bpre + (size_t)b * 4 * CHUNKS * BLK_U4;
#pragma unroll
    for (int g = 0; g < 6; g++) {
        uint4 v = (g == 0 || g == 3 || g == 5) ? vh : ((g == 2) ? vl : vm);
        int k6 = g * DD + ks * 8;
        prep_store(base, r, k6 >> 6, (k6 & 63) >> 3, v);
    }
}

// ============================ GEMM + argmax ============================
// CTA: 128x128 tile; 8 warps of 64x32; BK=64 double-buffered cp.async.
// grid: x = itile*4 + jtile (16), y = b (32).

#define SMEM_DYN (65536 + 512)

#define LDSM_X4(r0, r1, r2, r3, addr) \
    asm volatile("ldmatrix.sync.aligned.m8n8.x4.shared.b16 {%0,%1,%2,%3}, [%4];" \
                 : "=r"(r0), "=r"(r1), "=r"(r2), "=r"(r3) : "r"(addr))

#define MMA16816(c, a, b0, b1) \
    asm volatile("mma.sync.aligned.m16n8k16.row.col.f32.bf16.bf16.f32 " \
                 "{%0,%1,%2,%3}, {%4,%5,%6,%7}, {%8,%9}, {%0,%1,%2,%3};" \
                 : "+f"((c)[0]), "+f"((c)[1]), "+f"((c)[2]), "+f"((c)[3]) \
                 : "r"((a)[0]), "r"((a)[1]), "r"((a)[2]), "r"((a)[3]), \
                   "r"(b0), "r"(b1))

__global__ __launch_bounds__(256, 2) void k_gemm() {
    extern __shared__ __align__(16) char sm[];
    uint32_t smb = smem_u32(sm);
    int tid = threadIdx.x, lane = tid & 31, wid = tid >> 5;
    int bx = blockIdx.x;
    int itile = bx >> 2, jtile = bx & 3;
    int b = blockIdx.y;
    int warpM = (wid & 1) * 64, warpN = (wid >> 1) * 32;

    float* Inv = (float*)(sm + 65536);
    if (tid < 128) {
        int j = jtile * 128 + tid;
        Inv[tid] = (j < SQ) ? g_invn[b * SQ + j] : 0.f;
    }

    const char* Asrc = (const char*)(g_Apre + (size_t)(b * 4 + itile) * CHUNKS * BLK_U4);
    const char* Bsrc = (const char*)(g_Bpre + (size_t)(b * 4 + jtile) * CHUNKS * BLK_U4);

    float acc[4][4][4];
#pragma unroll
    for (int mt = 0; mt < 4; mt++)
#pragma unroll
        for (int n8 = 0; n8 < 4; n8++)
#pragma unroll
            for (int e = 0; e < 4; e++) acc[mt][n8][e] = 0.f;

#define STAGE_COPY(c, s) do {                                                   \
    uint32_t dA = smb + (s) * 32768 + tid * 16;                                 \
    const char* gA = Asrc + (size_t)(c) * 16384 + tid * 16;                     \
    const char* gB = Bsrc + (size_t)(c) * 16384 + tid * 16;                     \
    _Pragma("unroll")                                                           \
    for (int it = 0; it < 4; it++) {                                            \
        asm volatile("cp.async.cg.shared.global [%0], [%1], 16;"                \
                     :: "r"(dA + it * 4096), "l"(gA + it * 4096));              \
        asm volatile("cp.async.cg.shared.global [%0], [%1], 16;"                \
                     :: "r"(dA + 16384 + it * 4096), "l"(gB + it * 4096));      \
    }                                                                           \
    asm volatile("cp.async.commit_group;");                                     \
} while (0)

    STAGE_COPY(0, 0);
    STAGE_COPY(1, 1);

    int lrow = lane & 15, khalf = lane >> 4;           // A lane mapping
    int bg8 = lane >> 3, bl8 = lane & 7;               // B lane mapping
    int bRow0 = warpN + ((bg8 >> 1) << 3) + bl8;
    int bKg = bg8 & 1;

    for (int c = 0; c < CHUNKS; c++) {
        if (c < CHUNKS - 1) asm volatile("cp.async.wait_group 1;");
        else                asm volatile("cp.async.wait_group 0;");
        __syncthreads();
        uint32_t aB = smb + (c & 1) * 32768;
        uint32_t bBs = aB + 16384;
#pragma unroll
        for (int ks = 0; ks < 4; ks++) {
            uint32_t a[4][4];
#pragma unroll
            for (int mt = 0; mt < 4; mt++) {
                int row = warpM + mt * 16 + lrow;
                int kg  = ks * 2 + khalf;
                uint32_t ad = aB + row * 128 + ((kg ^ (row & 7)) << 4);
                LDSM_X4(a[mt][0], a[mt][1], a[mt][2], a[mt][3], ad);
            }
            uint32_t bb[2][4];
#pragma unroll
            for (int nb = 0; nb < 2; nb++) {
                int row = bRow0 + nb * 16;
                int kg  = ks * 2 + bKg;
                uint32_t ad = bBs + row * 128 + ((kg ^ (row & 7)) << 4);
                LDSM_X4(bb[nb][0], bb[nb][1], bb[nb][2], bb[nb][3], ad);
            }
#pragma unroll
            for (int mt = 0; mt < 4; mt++)
#pragma unroll
                for (int n8 = 0; n8 < 4; n8++)
                    MMA16816(acc[mt][n8], a[mt],
                             bb[n8 >> 1][(n8 & 1) * 2],
                             bb[n8 >> 1][(n8 & 1) * 2 + 1]);
        }
        __syncthreads();
        if (c + 2 < CHUNKS) STAGE_COPY(c + 2, c & 1);
    }

    // epilogue: per-row argmax with tgt inv-norm scaling
    int gid = lane >> 2, tig = lane & 3;
#pragma unroll
    for (int mt = 0; mt < 4; mt++) {
#pragma unroll
        for (int rh = 0; rh < 2; rh++) {
            int iloc = warpM + mt * 16 + gid + rh * 8;
            float best = NEG_INF;
            int bj = 0;
#pragma unroll
            for (int n8 = 0; n8 < 4; n8++) {
#pragma unroll
                for (int e = 0; e < 2; e++) {
                    int jloc = warpN + n8 * 8 + tig * 2 + e;
                    int j = jtile * 128 + jloc;
                    float v = acc[mt][n8][rh * 2 + e] * Inv[jloc];
                    if (j < SQ && v > best) { best = v; bj = j; }
                }
            }
#pragma unroll
            for (int o = 1; o <= 2; o <<= 1) {
                float ov = __shfl_xor_sync(0xffffffffu, best, o);
                int   oj = __shfl_xor_sync(0xffffffffu, bj, o);
                if (ov > best || (ov == best && oj < bj)) { best = ov; bj = oj; }
            }
            if (tig == 0) {
                int i = itile * 128 + iloc;
                if (i < SQ) {
                    uint32_t ub = __float_as_uint(best);
                    ub = ((int)ub >= 0) ? (ub | 0x80000000u) : ~ub;
                    unsigned long long p =
                        ((unsigned long long)ub << 32) | (uint32_t)(SQ - bj);
                    atomicMax(&g_pack[b * SQ + i], p);
                }
            }
        }
    }
#undef STAGE_COPY
}

__global__ void k_extract() {
    int n = blockIdx.x * blockDim.x + threadIdx.x;
    if (n < NROWS) g_idx[n] = SQ - (int)(g_pack[n] & 0xffffffffu);
}

// ============================ losses ============================

__global__ void k_imgloss(const float* __restrict__ image,
                          const float* __restrict__ target) {
    const int N4 = BB * SS * DD / 4;
    float s = 0.f;
    for (int i = blockIdx.x * blockDim.x + threadIdx.x; i < N4;
         i += gridDim.x * blockDim.x) {
        float4 a = reinterpret_cast<const float4*>(image)[i];
        float4 t = reinterpret_cast<const float4*>(target)[i];
        float dx = a.x - t.x, dy = a.y - t.y, dz = a.z - t.z, dw = a.w - t.w;
        s += dx * dx + dy * dy + dz * dz + dw * dw;
    }
#pragma unroll
    for (int o = 16; o > 0; o >>= 1) s += __shfl_xor_sync(0xffffffffu, s, o);
    __shared__ float warp_s[8];
    int wd = threadIdx.x >> 5, lane = threadIdx.x & 31;
    if (lane == 0) warp_s[wd] = s;
    __syncthreads();
    if (wd == 0) {
        s = (lane < (blockDim.x >> 5)) ? warp_s[lane] : 0.f;
#pragma unroll
        for (int o = 4; o > 0; o >>= 1) s += __shfl_xor_sync(0xffffffffu, s, o);
        if (lane == 0) atomicAdd(&g_img_sum, s);
    }
}

__global__ void k_txtloss(const float* __restrict__ text,
                          const float* __restrict__ target,
                          const int* __restrict__ pm) {
    int row = blockIdx.x * (blockDim.x >> 5) + (threadIdx.x >> 5);
    if (row >= NROWS) return;
    int lane = threadIdx.x & 31;
    int b = row / SQ, i = row % SQ;
    if (pm[b * SS + i + 1] != 0) return;
    int id = g_idx[row];
    const float4* pt = reinterpret_cast<const float4*>(
        text + (size_t)b * SS * DD + (size_t)(i + 1) * DD);
    const float4* pa = reinterpret_cast<const float4*>(
        target + (size_t)b * SS * DD + (size_t)(id + 1) * DD);
    float s = 0.f;
#pragma unroll
    for (int it = 0; it < DD / 128; it++) {
        float4 a = pt[lane + it * 32];
        float4 c = pa[lane + it * 32];
        float dx = a.x - c.x, dy = a.y - c.y, dz = a.z - c.z, dw = a.w - c.w;
        s += dx * dx + dy * dy + dz * dz + dw * dw;
    }
#pragma unroll
    for (int o = 16; o > 0; o >>= 1) s += __shfl_xor_sync(0xffffffffu, s, o);
    if (lane == 0) {
        atomicAdd(&g_txt_sum, s);
        atomicAdd(&g_valid, 1);
    }
}

__global__ void k_finalize(float* __restrict__ out) {
    float kt = g_txt_sum / ((float)g_valid * (float)DD);
    float ki = g_img_sum / (float)(BB * SS * DD);
    out[0] = 0.5f * (kt + ki);
    out[1] = kt;
    out[2] = ki;
}

__global__ void k_idxcopy(float* __restrict__ out) {
    int n = blockIdx.x * blockDim.x + threadIdx.x;
    if (n < NROWS) out[3 + n] = (float)g_idx[n];
}

// ============================ launch ============================

extern "C" void kernel_launch(void* const* d_in, const int* in_sizes, int n_in,
                              void* d_out, int out_size) {
    const float* image  = (const float*)d_in[0];
    const float* text   = (const float*)d_in[1];
    const float* target = (const float*)d_in[2];
    const int*   pm     = (const int*)d_in[3];
    float* out = (float*)d_out;

    k_init<<<(NROWS + 255) / 256, 256>>>();
    k_prep_A<<<(BB * 512 * 96 + 255) / 256, 256>>>(text);
    k_prep_B<<<(BB * 512 * 96 + 255) / 256, 256>>>(target);
    k_invnorm<<<(NROWS + 3) / 4, 128>>>(target);

    cudaFuncSetAttribute(k_gemm, cudaFuncAttributeMaxDynamicSharedMemorySize, SMEM_DYN);
    k_gemm<<<dim3(16, BB), 256, SMEM_DYN>>>();

    k_extract<<<(NROWS + 255) / 256, 256>>>();
    k_imgloss<<<1184, 256>>>(image, target);
    k_txtloss<<<(NROWS + 3) / 4, 128>>>(text, target, pm);
    k_finalize<<<1, 1>>>(out);
    k_idxcopy<<<(NROWS + 255) / 256, 256>>>(out);
}